// round 12
// baseline (speedup 1.0000x reference)
#include <cuda_runtime.h>

// GCN 2-layer, scatter-reassociated + normalization-reassociated.
//
// t[d]  = dinv[d] * ( dinv[d]*x[d] + sum_e ew * dinv[s]*x[s] )
// out[d]= dinv[d] * ( dinv[d]*hw[d] + sum_e ew * dinv[s]*hw[s] ) + b2
//
// Locked shape (R11, 81.95us): 1 edge/thread flat grids, PDL, minimal edge
// bodies (regs=16), k_deg sync-free. Measured & rejected: 4-edge vector (R3),
// grid-stride (R5), L1 hints (R7), 2-edge pairing (R8), TPB=128 (R9),
// prefetch-before-sync (R10). Edge passes ~90% of L1tex random-wavefront
// floor; 5 random sector-ops/edge is the algorithmic minimum.
//
// R12: block-size sweep closure — edge kernels at TPB=512 (6250 blocks vs
// 12500) to halve block dispatch / PDL prologue count at constant thread
// count. Node kernels remain 256.

#define NMAX 131072
#define TPB_E 512
#define TPB_N 256

__device__ float  g_deg[NMAX];    // edge-weight sums; zeroed by k_node1 each call
__device__ float  g_dinv[NMAX];   // rsqrt(deg)
__device__ float2 g_xd[NMAX];     // dinv[i] * x[i]          (gather source)
__device__ float2 g_u[NMAX];      // scatter target layer 1  (init = xd)
__device__ float  g_hws[NMAX];    // dinv[i] * hw[i]         (gather source)

__device__ __forceinline__ void pdl_prologue() {
    cudaGridDependencySynchronize();            // wait for predecessor's writes
    cudaTriggerProgrammaticLaunchCompletion();  // let successor prelaunch early
}

// ---- kernel 1: deg[dst] += ew  (no grid-sync: independent of predecessor) --
__global__ void __launch_bounds__(TPB_E) k_deg(const int* __restrict__ dst,
                                               const float* __restrict__ ew, int E) {
    cudaTriggerProgrammaticLaunchCompletion();
    int e = blockIdx.x * blockDim.x + threadIdx.x;
    if (e < E) atomicAdd(&g_deg[dst[e]], ew[e]);
}

// ---- kernel 2: dinv = rsqrt(deg+1); reset deg; xd = dinv*x; u init = xd ----
__global__ void __launch_bounds__(TPB_N) k_node1(const float2* __restrict__ x, int n) {
    pdl_prologue();
    int i = blockIdx.x * blockDim.x + threadIdx.x;
    if (i >= n) return;
    float d = g_deg[i] + 1.0f;      // +1: self-loop weight; always > 0
    g_deg[i] = 0.0f;                // reset for next graph replay
    float r = rsqrtf(d);
    g_dinv[i] = r;
    float2 xv = x[i];
    float2 xd = make_float2(r * xv.x, r * xv.y);
    g_xd[i] = xd;
    g_u[i]  = xd;   // self-loop term (outer dinv applied later)
}

// ---- kernel 3: layer-1 edge scatter: u[d] += ew * xd[s] ---------------------
__global__ void __launch_bounds__(TPB_E) k_edge1(const int* __restrict__ src,
                                                 const int* __restrict__ dst,
                                                 const float* __restrict__ ew, int E) {
    pdl_prologue();
    int e = blockIdx.x * blockDim.x + threadIdx.x;
    if (e >= E) return;
    int s = src[e];
    int d = dst[e];
    float w = ew[e];
    float2 xd = __ldg(&g_xd[s]);
    float a = w * xd.x;
    float b = w * xd.y;
    asm volatile("red.global.add.v2.f32 [%0], {%1, %2};"
                 :: "l"(&g_u[d]), "f"(a), "f"(b) : "memory");
}

// ---- kernel 4: t = dinv*u; MLP; hws = dinv*hw; out init = hws ---------------
__global__ void __launch_bounds__(TPB_N) k_node2(const float4* __restrict__ W1,  // [2,16] as 8 float4
                                                 const float4* __restrict__ b1,  // [16]   as 4 float4
                                                 const float4* __restrict__ W2,  // [16]   as 4 float4
                                                 float* __restrict__ out, int n) {
    pdl_prologue();
    int i = blockIdx.x * blockDim.x + threadIdx.x;
    if (i >= n) return;
    float r = g_dinv[i];
    float2 u = g_u[i];
    float tx = r * u.x;
    float ty = r * u.y;
    float acc = 0.0f;
#pragma unroll
    for (int q = 0; q < 4; q++) {
        float4 w1a = __ldg(&W1[q]);        // W1[0][4q..4q+3]
        float4 w1b = __ldg(&W1[4 + q]);    // W1[1][4q..4q+3]
        float4 bb  = __ldg(&b1[q]);
        float4 w2  = __ldg(&W2[q]);
        float h0 = fmaxf(fmaf(tx, w1a.x, fmaf(ty, w1b.x, bb.x)), 0.0f);
        float h1 = fmaxf(fmaf(tx, w1a.y, fmaf(ty, w1b.y, bb.y)), 0.0f);
        float h2 = fmaxf(fmaf(tx, w1a.z, fmaf(ty, w1b.z, bb.z)), 0.0f);
        float h3 = fmaxf(fmaf(tx, w1a.w, fmaf(ty, w1b.w, bb.w)), 0.0f);
        acc = fmaf(h0, w2.x, fmaf(h1, w2.y, fmaf(h2, w2.z, fmaf(h3, w2.w, acc))));
    }
    float hws = r * acc;
    g_hws[i] = hws;
    out[i]   = hws;   // self-loop init (outer dinv + b2 applied in k_node3)
}

// ---- kernel 5: layer-2 edge scatter: out[d] += ew * hws[s] ------------------
__global__ void __launch_bounds__(TPB_E) k_edge2(const int* __restrict__ src,
                                                 const int* __restrict__ dst,
                                                 const float* __restrict__ ew,
                                                 float* __restrict__ out, int E) {
    pdl_prologue();
    int e = blockIdx.x * blockDim.x + threadIdx.x;
    if (e >= E) return;
    int s = src[e];
    int d = dst[e];
    atomicAdd(&out[d], ew[e] * __ldg(&g_hws[s]));
}

// ---- kernel 6: out = dinv*out + b2 ------------------------------------------
__global__ void __launch_bounds__(TPB_N) k_node3(const float* __restrict__ b2,
                                                 float* __restrict__ out, int n) {
    pdl_prologue();
    int i = blockIdx.x * blockDim.x + threadIdx.x;
    if (i >= n) return;
    out[i] = fmaf(g_dinv[i], out[i], __ldg(&b2[0]));
}

// ---- host: launch all kernels with programmatic stream serialization --------
template <typename F, typename... Args>
static void launch_pdl(F kernel, int nblocks, int tpb, Args... args) {
    cudaLaunchConfig_t cfg = {};
    cfg.gridDim  = dim3((unsigned)nblocks, 1, 1);
    cfg.blockDim = dim3((unsigned)tpb, 1, 1);
    cfg.dynamicSmemBytes = 0;
    cfg.stream = 0;
    cudaLaunchAttribute attr[1];
    attr[0].id = cudaLaunchAttributeProgrammaticStreamSerialization;
    attr[0].val.programmaticStreamSerializationAllowed = 1;
    cfg.attrs = attr;
    cfg.numAttrs = 1;
    cudaLaunchKernelEx(&cfg, kernel, args...);
}

extern "C" void kernel_launch(void* const* d_in, const int* in_sizes, int n_in,
                              void* d_out, int out_size) {
    const float* x  = (const float*)d_in[0];   // [N, 2]
    const int*   ei = (const int*)d_in[1];     // [2, E]
    const float* ew = (const float*)d_in[2];   // [E]
    const float* W1 = (const float*)d_in[3];   // [2, 16]
    const float* b1 = (const float*)d_in[4];   // [16]
    const float* W2 = (const float*)d_in[5];   // [16, 1]
    const float* b2 = (const float*)d_in[6];   // [1]
    float* out = (float*)d_out;                // [N, 1]

    int n = in_sizes[0] / 2;
    int E = in_sizes[2];
    const int* src = ei;
    const int* dst = ei + E;

    int nb_n = (n + TPB_N - 1) / TPB_N;
    int nb_e = (E + TPB_E - 1) / TPB_E;

    launch_pdl(k_deg,   nb_e, TPB_E, dst, ew, E);
    launch_pdl(k_node1, nb_n, TPB_N, (const float2*)x, n);
    launch_pdl(k_edge1, nb_e, TPB_E, src, dst, ew, E);
    launch_pdl(k_node2, nb_n, TPB_N, (const float4*)W1, (const float4*)b1,
                              (const float4*)W2, out, n);
    launch_pdl(k_edge2, nb_e, TPB_E, src, dst, ew, out, E);
    launch_pdl(k_node3, nb_n, TPB_N, b2, out, n);
}

// round 13
// speedup vs baseline: 1.0059x; 1.0059x over previous
#include <cuda_runtime.h>

// GCN 2-layer, scatter-reassociated + normalization-reassociated. FINAL.
//
// t[d]  = dinv[d] * ( dinv[d]*x[d] + sum_e ew * dinv[s]*x[s] )
// out[d]= dinv[d] * ( dinv[d]*hw[d] + sum_e ew * dinv[s]*hw[s] ) + b2
//
// Locked shape (R11, 81.95us): 1 edge/thread flat TPB=256 grids, PDL,
// minimal edge bodies (regs=16), k_deg sync-free.
// Measured & rejected: 4-edge vector (R3: 88.3), grid-stride persistent
// (R5: 96.3), L1 cache hints (R7: neutral), 2-edge scalar pairing (R8: 82.9),
// TPB=128 (R9: 90.1), prefetch-before-sync (R10: 82.7), TPB=512 (R12: 82.2).
// Edge passes run at ~90% of the L1tex random-wavefront floor; 5 random
// sector-ops/edge is the algorithmic minimum for symmetric GCN normalization.

#define NMAX 131072
#define TPB 256

__device__ float  g_deg[NMAX];    // edge-weight sums; zeroed by k_node1 each call
__device__ float  g_dinv[NMAX];   // rsqrt(deg)
__device__ float2 g_xd[NMAX];     // dinv[i] * x[i]          (gather source)
__device__ float2 g_u[NMAX];      // scatter target layer 1  (init = xd)
__device__ float  g_hws[NMAX];    // dinv[i] * hw[i]         (gather source)

__device__ __forceinline__ void pdl_prologue() {
    cudaGridDependencySynchronize();            // wait for predecessor's writes
    cudaTriggerProgrammaticLaunchCompletion();  // let successor prelaunch early
}

// ---- kernel 1: deg[dst] += ew  (no grid-sync: independent of predecessor) --
__global__ void __launch_bounds__(TPB) k_deg(const int* __restrict__ dst,
                                             const float* __restrict__ ew, int E) {
    cudaTriggerProgrammaticLaunchCompletion();
    int e = blockIdx.x * blockDim.x + threadIdx.x;
    if (e < E) atomicAdd(&g_deg[dst[e]], ew[e]);
}

// ---- kernel 2: dinv = rsqrt(deg+1); reset deg; xd = dinv*x; u init = xd ----
__global__ void __launch_bounds__(TPB) k_node1(const float2* __restrict__ x, int n) {
    pdl_prologue();
    int i = blockIdx.x * blockDim.x + threadIdx.x;
    if (i >= n) return;
    float d = g_deg[i] + 1.0f;      // +1: self-loop weight; always > 0
    g_deg[i] = 0.0f;                // reset for next graph replay
    float r = rsqrtf(d);
    g_dinv[i] = r;
    float2 xv = x[i];
    float2 xd = make_float2(r * xv.x, r * xv.y);
    g_xd[i] = xd;
    g_u[i]  = xd;   // self-loop term (outer dinv applied later)
}

// ---- kernel 3: layer-1 edge scatter: u[d] += ew * xd[s] ---------------------
__global__ void __launch_bounds__(TPB) k_edge1(const int* __restrict__ src,
                                               const int* __restrict__ dst,
                                               const float* __restrict__ ew, int E) {
    pdl_prologue();
    int e = blockIdx.x * blockDim.x + threadIdx.x;
    if (e >= E) return;
    int s = src[e];
    int d = dst[e];
    float w = ew[e];
    float2 xd = __ldg(&g_xd[s]);
    float a = w * xd.x;
    float b = w * xd.y;
    asm volatile("red.global.add.v2.f32 [%0], {%1, %2};"
                 :: "l"(&g_u[d]), "f"(a), "f"(b) : "memory");
}

// ---- kernel 4: t = dinv*u; MLP; hws = dinv*hw; out init = hws ---------------
__global__ void __launch_bounds__(TPB) k_node2(const float4* __restrict__ W1,  // [2,16] as 8 float4
                                               const float4* __restrict__ b1,  // [16]   as 4 float4
                                               const float4* __restrict__ W2,  // [16]   as 4 float4
                                               float* __restrict__ out, int n) {
    pdl_prologue();
    int i = blockIdx.x * blockDim.x + threadIdx.x;
    if (i >= n) return;
    float r = g_dinv[i];
    float2 u = g_u[i];
    float tx = r * u.x;
    float ty = r * u.y;
    float acc = 0.0f;
#pragma unroll
    for (int q = 0; q < 4; q++) {
        float4 w1a = __ldg(&W1[q]);        // W1[0][4q..4q+3]
        float4 w1b = __ldg(&W1[4 + q]);    // W1[1][4q..4q+3]
        float4 bb  = __ldg(&b1[q]);
        float4 w2  = __ldg(&W2[q]);
        float h0 = fmaxf(fmaf(tx, w1a.x, fmaf(ty, w1b.x, bb.x)), 0.0f);
        float h1 = fmaxf(fmaf(tx, w1a.y, fmaf(ty, w1b.y, bb.y)), 0.0f);
        float h2 = fmaxf(fmaf(tx, w1a.z, fmaf(ty, w1b.z, bb.z)), 0.0f);
        float h3 = fmaxf(fmaf(tx, w1a.w, fmaf(ty, w1b.w, bb.w)), 0.0f);
        acc = fmaf(h0, w2.x, fmaf(h1, w2.y, fmaf(h2, w2.z, fmaf(h3, w2.w, acc))));
    }
    float hws = r * acc;
    g_hws[i] = hws;
    out[i]   = hws;   // self-loop init (outer dinv + b2 applied in k_node3)
}

// ---- kernel 5: layer-2 edge scatter: out[d] += ew * hws[s] ------------------
__global__ void __launch_bounds__(TPB) k_edge2(const int* __restrict__ src,
                                               const int* __restrict__ dst,
                                               const float* __restrict__ ew,
                                               float* __restrict__ out, int E) {
    pdl_prologue();
    int e = blockIdx.x * blockDim.x + threadIdx.x;
    if (e >= E) return;
    int s = src[e];
    int d = dst[e];
    atomicAdd(&out[d], ew[e] * __ldg(&g_hws[s]));
}

// ---- kernel 6: out = dinv*out + b2 ------------------------------------------
__global__ void __launch_bounds__(TPB) k_node3(const float* __restrict__ b2,
                                               float* __restrict__ out, int n) {
    pdl_prologue();
    int i = blockIdx.x * blockDim.x + threadIdx.x;
    if (i >= n) return;
    out[i] = fmaf(g_dinv[i], out[i], __ldg(&b2[0]));
}

// ---- host: launch all kernels with programmatic stream serialization --------
template <typename F, typename... Args>
static void launch_pdl(F kernel, int nblocks, Args... args) {
    cudaLaunchConfig_t cfg = {};
    cfg.gridDim  = dim3((unsigned)nblocks, 1, 1);
    cfg.blockDim = dim3(TPB, 1, 1);
    cfg.dynamicSmemBytes = 0;
    cfg.stream = 0;
    cudaLaunchAttribute attr[1];
    attr[0].id = cudaLaunchAttributeProgrammaticStreamSerialization;
    attr[0].val.programmaticStreamSerializationAllowed = 1;
    cfg.attrs = attr;
    cfg.numAttrs = 1;
    cudaLaunchKernelEx(&cfg, kernel, args...);
}

extern "C" void kernel_launch(void* const* d_in, const int* in_sizes, int n_in,
                              void* d_out, int out_size) {
    const float* x  = (const float*)d_in[0];   // [N, 2]
    const int*   ei = (const int*)d_in[1];     // [2, E]
    const float* ew = (const float*)d_in[2];   // [E]
    const float* W1 = (const float*)d_in[3];   // [2, 16]
    const float* b1 = (const float*)d_in[4];   // [16]
    const float* W2 = (const float*)d_in[5];   // [16, 1]
    const float* b2 = (const float*)d_in[6];   // [1]
    float* out = (float*)d_out;                // [N, 1]

    int n = in_sizes[0] / 2;
    int E = in_sizes[2];
    const int* src = ei;
    const int* dst = ei + E;

    int nb_n = (n + TPB - 1) / TPB;
    int nb_e = (E + TPB - 1) / TPB;

    launch_pdl(k_deg,   nb_e, dst, ew, E);
    launch_pdl(k_node1, nb_n, (const float2*)x, n);
    launch_pdl(k_edge1, nb_e, src, dst, ew, E);
    launch_pdl(k_node2, nb_n, (const float4*)W1, (const float4*)b1,
                              (const float4*)W2, out, n);
    launch_pdl(k_edge2, nb_e, src, dst, ew, out, E);
    launch_pdl(k_node3, nb_n, b2, out, n);
}